// round 4
// baseline (speedup 1.0000x reference)
#include <cuda_runtime.h>
#include <cuda_bf16.h>
#include <math.h>

// ---------------------------------------------------------------------------
// SimplifiedSSMLayer: B=8, S=4096, D_MODEL=1024, D_STATE=16
// Round 4: GEMM occupancy fix (BK=16, 4-stage, 80KB smem -> 2 CTAs/SM).
// ---------------------------------------------------------------------------

#define BATCH   8
#define SEQ     4096
#define DM      1024
#define NS      16
#define T_TOK   (BATCH*SEQ)          // 32768

__device__ float g_Bx[T_TOK * NS];               // 2 MB
__device__ float g_states[T_TOK * NS];           // 2 MB
__device__ float g_gate[(size_t)T_TOK * DM];     // 128 MB

// ---------------------------------------------------------------------------
// K1: Bx = x @ B_w^T + B_b   (512 blocks x 64 tokens)
// ---------------------------------------------------------------------------
__global__ void __launch_bounds__(256) bx_kernel(const float* __restrict__ x,
                                                 const float* __restrict__ B_w,
                                                 const float* __restrict__ B_b)
{
    extern __shared__ float Bw_s[];  // [16][1024]
    const int tid = threadIdx.x;
    for (int i = tid; i < (NS * DM) / 4; i += 256)
        reinterpret_cast<float4*>(Bw_s)[i] = reinterpret_cast<const float4*>(B_w)[i];
    __syncthreads();

    const int w = tid >> 5, lane = tid & 31;
    const int tbase = blockIdx.x * 64 + w * 8;

    for (int g = 0; g < 2; ++g) {
        const int t0 = tbase + g * 4;
        float acc[4][NS];
#pragma unroll
        for (int tt = 0; tt < 4; ++tt)
#pragma unroll
            for (int n = 0; n < NS; ++n) acc[tt][n] = 0.f;

#pragma unroll 2
        for (int c = 0; c < 8; ++c) {
            const int k0 = c * 128 + lane * 4;
            float4 xv[4];
#pragma unroll
            for (int tt = 0; tt < 4; ++tt)
                xv[tt] = *reinterpret_cast<const float4*>(&x[(size_t)(t0 + tt) * DM + k0]);
#pragma unroll
            for (int n = 0; n < NS; ++n) {
                const float4 bw = *reinterpret_cast<const float4*>(&Bw_s[n * DM + k0]);
#pragma unroll
                for (int tt = 0; tt < 4; ++tt) {
                    acc[tt][n] = fmaf(xv[tt].x, bw.x, acc[tt][n]);
                    acc[tt][n] = fmaf(xv[tt].y, bw.y, acc[tt][n]);
                    acc[tt][n] = fmaf(xv[tt].z, bw.z, acc[tt][n]);
                    acc[tt][n] = fmaf(xv[tt].w, bw.w, acc[tt][n]);
                }
            }
        }
#pragma unroll
        for (int tt = 0; tt < 4; ++tt) {
            float outv = 0.f;
#pragma unroll
            for (int n = 0; n < NS; ++n) {
                float v = acc[tt][n];
                v += __shfl_xor_sync(0xffffffffu, v, 16);
                v += __shfl_xor_sync(0xffffffffu, v, 8);
                v += __shfl_xor_sync(0xffffffffu, v, 4);
                v += __shfl_xor_sync(0xffffffffu, v, 2);
                v += __shfl_xor_sync(0xffffffffu, v, 1);
                if (lane == n) outv = v;
            }
            if (lane < NS)
                g_Bx[(size_t)(t0 + tt) * NS + lane] = outv + B_b[lane];
        }
    }
}

// ---------------------------------------------------------------------------
// K2: scan (blocks 0..63) + tf32 mma.sync gate GEMM (blocks 64..2111)
// GEMM: 128x128 CTA tile, BK=16, 4-stage cp.async pipeline, 80KB smem,
//       honest 2 CTAs/SM. 8 warps (4M x 2N), warp tile 32x64.
// ---------------------------------------------------------------------------
#define GTM 128
#define GTN 128
#define GBK 16
#define GSTAGES (DM / GBK)                // 64
#define N_MTILES (T_TOK / GTM)            // 256
#define N_NTILES (DM / GTN)               // 8
#define GEMM_BLOCKS (N_MTILES * N_NTILES) // 2048
#define SCAN_BLOCKS 64

#define ROWSTRIDE 20                      // 16 k-floats + 4 pad
#define A_FLOATS (GTM * ROWSTRIDE)        // 2560
#define STAGE_FLOATS (2 * A_FLOATS)       // 5120
#define STAGE_BYTES (STAGE_FLOATS * 4)    // 20480
#define NPIPE 4
#define GEMM_SMEM (NPIPE * STAGE_BYTES)   // 81920

#define SCAN_CHUNK 64
#define SCAN_WARM  64

__device__ __forceinline__ unsigned smem_u32(const void* p) {
    unsigned a;
    asm("{ .reg .u64 t; cvta.to.shared.u64 t, %1; cvt.u32.u64 %0, t; }"
        : "=r"(a) : "l"(p));
    return a;
}
__device__ __forceinline__ void cp16(unsigned dst, const void* src) {
    asm volatile("cp.async.cg.shared.global [%0], [%1], 16;"
                 :: "r"(dst), "l"(src) : "memory");
}

__global__ void __launch_bounds__(256, 2) gemm_scan_kernel(
    const float* __restrict__ x, const float* __restrict__ A,
    const float* __restrict__ gate_w, const float* __restrict__ gate_b)
{
    extern __shared__ float smemf[];

    if (blockIdx.x < SCAN_BLOCKS) {
        // ------------------ parallel scan (contraction warm-up) ------------
        if (threadIdx.x >= 128) return;
        const int sb = blockIdx.x;
        const int warp = threadIdx.x >> 5, lane = threadIdx.x & 31;
        const int chunk = sb * 8 + warp * 2 + (lane >> 4); // 0..511
        const int i = lane & 15;
        const int batch = chunk >> 6;
        const int cib = chunk & 63;
        const int t0 = cib * SCAN_CHUNK;
        const int ts = (cib == 0) ? 0 : (t0 - SCAN_WARM);

        float a[NS];
#pragma unroll
        for (int j = 0; j < NS; ++j) a[j] = __ldg(&A[i * NS + j]);

        const float* bxp = g_Bx + (size_t)batch * SEQ * NS;
        float* stp = g_states + (size_t)batch * SEQ * NS;
        float s = 0.f;
        for (int t = ts; t < t0 + SCAN_CHUNK; ++t) {
            const float bx = bxp[t * NS + i];
            float sv[NS];
#pragma unroll
            for (int j = 0; j < NS; ++j) sv[j] = __shfl_sync(0xffffffffu, s, j, 16);
            float p0 = fmaf(a[0], sv[0], fmaf(a[1], sv[1], fmaf(a[2], sv[2], a[3] * sv[3])));
            float p1 = fmaf(a[4], sv[4], fmaf(a[5], sv[5], fmaf(a[6], sv[6], a[7] * sv[7])));
            float p2 = fmaf(a[8], sv[8], fmaf(a[9], sv[9], fmaf(a[10], sv[10], a[11] * sv[11])));
            float p3 = fmaf(a[12], sv[12], fmaf(a[13], sv[13], fmaf(a[14], sv[14], a[15] * sv[15])));
            s = tanhf(bx + ((p0 + p1) + (p2 + p3)));
            if (t >= t0) stp[t * NS + i] = s;
        }
        return;
    }

    // ------------------------- GEMM path --------------------------------
    const int tile = blockIdx.x - SCAN_BLOCKS;
    const int m0 = (tile >> 3) * GTM;
    const int n0 = (tile & 7) * GTN;

    const int tid = threadIdx.x;
    const int wid = tid >> 5;
    const int lane = tid & 31;
    const int wm = (wid & 3) * 32;      // warp M offset in tile
    const int wn = (wid >> 2) * 64;     // warp N offset in tile
    const int lq = lane >> 2;           // lane/4 : 0..7
    const int lr = lane & 3;            // lane%4 : 0..3

    const unsigned sbase = smem_u32(smemf);

    // --- cp.async stage issue: 16KB per stage (A 8KB + B 8KB) ---
    auto cp_stage = [&](int s) {
        const int kc = s * GBK;
        const unsigned sA = sbase + (unsigned)(s & 3) * STAGE_BYTES;
        const unsigned sB = sA + A_FLOATS * 4;
#pragma unroll
        for (int q = 0; q < 2; ++q) {
            const int j = tid + 256 * q;
            const int row = j >> 2;
            const int kg = j & 3;
            cp16(sA + row * (ROWSTRIDE * 4) + kg * 16,
                 &x[(size_t)(m0 + row) * DM + kc + kg * 4]);
            cp16(sB + row * (ROWSTRIDE * 4) + kg * 16,
                 &gate_w[(size_t)(n0 + row) * DM + kc + kg * 4]);
        }
        asm volatile("cp.async.commit_group;" ::: "memory");
    };

    float c[2][8][4];
#pragma unroll
    for (int mi = 0; mi < 2; ++mi)
#pragma unroll
        for (int ni = 0; ni < 8; ++ni)
#pragma unroll
            for (int r = 0; r < 4; ++r) c[mi][ni][r] = 0.f;

    cp_stage(0);
    cp_stage(1);
    cp_stage(2);

    for (int s = 0; s < GSTAGES; ++s) {
        asm volatile("cp.async.wait_group 2;" ::: "memory");
        __syncthreads();

        const unsigned* Asu = reinterpret_cast<const unsigned*>(
            smemf + (s & 3) * STAGE_FLOATS);
        const unsigned* Bsu = Asu + A_FLOATS;

#pragma unroll
        for (int ks = 0; ks < 2; ++ks) {
            const int k0 = ks * 8;
            unsigned af[2][4];
#pragma unroll
            for (int mi = 0; mi < 2; ++mi) {
                const int r0 = (wm + mi * 16 + lq) * ROWSTRIDE + k0 + lr;
                af[mi][0] = Asu[r0];
                af[mi][1] = Asu[r0 + 8 * ROWSTRIDE];
                af[mi][2] = Asu[r0 + 4];
                af[mi][3] = Asu[r0 + 8 * ROWSTRIDE + 4];
            }
            unsigned bf[8][2];
#pragma unroll
            for (int ni = 0; ni < 8; ++ni) {
                const int rb = (wn + ni * 8 + lq) * ROWSTRIDE + k0 + lr;
                bf[ni][0] = Bsu[rb];
                bf[ni][1] = Bsu[rb + 4];
            }
#pragma unroll
            for (int mi = 0; mi < 2; ++mi)
#pragma unroll
                for (int ni = 0; ni < 8; ++ni) {
                    asm volatile(
                        "mma.sync.aligned.m16n8k8.row.col.f32.tf32.tf32.f32 "
                        "{%0,%1,%2,%3}, {%4,%5,%6,%7}, {%8,%9}, {%0,%1,%2,%3};"
                        : "+f"(c[mi][ni][0]), "+f"(c[mi][ni][1]),
                          "+f"(c[mi][ni][2]), "+f"(c[mi][ni][3])
                        : "r"(af[mi][0]), "r"(af[mi][1]),
                          "r"(af[mi][2]), "r"(af[mi][3]),
                          "r"(bf[ni][0]), "r"(bf[ni][1]));
                }
        }
        if (s + 3 < GSTAGES) cp_stage(s + 3);
    }

    // --- epilogue: silu(acc + gate_b) -> g_gate ---
#pragma unroll
    for (int ni = 0; ni < 8; ++ni) {
        const int col = n0 + wn + ni * 8 + lr * 2;
        const float2 gb = *reinterpret_cast<const float2*>(&gate_b[col]);
#pragma unroll
        for (int mi = 0; mi < 2; ++mi) {
            const int row0 = m0 + wm + mi * 16 + lq;
#pragma unroll
            for (int h = 0; h < 2; ++h) {
                const int row = row0 + h * 8;
                float z0 = c[mi][ni][h * 2 + 0] + gb.x;
                float z1 = c[mi][ni][h * 2 + 1] + gb.y;
                float2 o;
                o.x = z0 / (1.0f + __expf(-z0));
                o.y = z1 / (1.0f + __expf(-z1));
                *reinterpret_cast<float2*>(&g_gate[(size_t)row * DM + col]) = o;
            }
        }
    }
}

// ---------------------------------------------------------------------------
// K3: fused  so = states@C_w^T + C_b + D*x ; o = g*so+(1-g)*x ; r = o+x ; LN
// ---------------------------------------------------------------------------
__global__ void __launch_bounds__(256) combine_ln_kernel(
    const float* __restrict__ x, const float* __restrict__ C_w,
    const float* __restrict__ C_b, const float* __restrict__ Dv,
    const float* __restrict__ ln_g, const float* __restrict__ ln_b,
    float* __restrict__ out)
{
    __shared__ float st_s[8][NS];
    __shared__ float r_s[8][DM];
    __shared__ float wsum[8][8], wsq[8][8];
    __shared__ float mu_s[8], rs_s[8];

    const int tid = threadIdx.x;
    const int tok0 = blockIdx.x * 8;

    if (tid < 128)
        st_s[tid >> 4][tid & 15] =
            g_states[(size_t)(tok0 + (tid >> 4)) * NS + (tid & 15)];

    float cw[4][NS], cb[4], dv[4], lg[4], lb[4];
#pragma unroll
    for (int q = 0; q < 4; ++q) {
        const int e = tid + q * 256;
#pragma unroll
        for (int n4 = 0; n4 < 4; ++n4) {
            const float4 v = *reinterpret_cast<const float4*>(&C_w[e * NS + n4 * 4]);
            cw[q][n4 * 4 + 0] = v.x;
            cw[q][n4 * 4 + 1] = v.y;
            cw[q][n4 * 4 + 2] = v.z;
            cw[q][n4 * 4 + 3] = v.w;
        }
        cb[q] = C_b[e];
        dv[q] = Dv[e];
        lg[q] = ln_g[e];
        lb[q] = ln_b[e];
    }
    __syncthreads();

    const int warp = tid >> 5, lane = tid & 31;
    for (int r = 0; r < 8; ++r) {
        const size_t t = (size_t)(tok0 + r);
        float ps = 0.f, pq = 0.f;
#pragma unroll
        for (int q = 0; q < 4; ++q) {
            const int e = tid + q * 256;
            const float xv = x[t * DM + e];
            const float gv = g_gate[t * DM + e];
            float so = cb[q];
#pragma unroll
            for (int n = 0; n < NS; ++n) so = fmaf(st_s[r][n], cw[q][n], so);
            so = fmaf(dv[q], xv, so);
            const float o = fmaf(gv, so - xv, xv);
            const float rr = o + xv;
            r_s[r][e] = rr;
            ps += rr;
            pq += rr * rr;
        }
#pragma unroll
        for (int off = 16; off; off >>= 1) {
            ps += __shfl_xor_sync(0xffffffffu, ps, off);
            pq += __shfl_xor_sync(0xffffffffu, pq, off);
        }
        if (lane == 0) { wsum[r][warp] = ps; wsq[r][warp] = pq; }
    }
    __syncthreads();

    if (tid < 8) {
        float s = 0.f, s2 = 0.f;
#pragma unroll
        for (int w = 0; w < 8; ++w) { s += wsum[tid][w]; s2 += wsq[tid][w]; }
        const float mu = s * (1.0f / DM);
        float var = s2 * (1.0f / DM) - mu * mu;
        var = fmaxf(var, 0.f);
        mu_s[tid] = mu;
        rs_s[tid] = rsqrtf(var + 1e-5f);
    }
    __syncthreads();

    for (int r = 0; r < 8; ++r) {
        const size_t t = (size_t)(tok0 + r);
        const float mu = mu_s[r], rs = rs_s[r];
#pragma unroll
        for (int q = 0; q < 4; ++q) {
            const int e = tid + q * 256;
            out[t * DM + e] = (r_s[r][e] - mu) * rs * lg[q] + lb[q];
        }
    }
}

// ---------------------------------------------------------------------------
extern "C" void kernel_launch(void* const* d_in, const int* in_sizes, int n_in,
                              void* d_out, int out_size)
{
    const float* x      = (const float*)d_in[0];
    const float* A      = (const float*)d_in[1];
    const float* B_w    = (const float*)d_in[2];
    const float* B_b    = (const float*)d_in[3];
    const float* C_w    = (const float*)d_in[4];
    const float* C_b    = (const float*)d_in[5];
    const float* Dv     = (const float*)d_in[6];
    const float* gate_w = (const float*)d_in[7];
    const float* gate_b = (const float*)d_in[8];
    const float* ln_g   = (const float*)d_in[9];
    const float* ln_b   = (const float*)d_in[10];
    float* out = (float*)d_out;

    cudaFuncSetAttribute(bx_kernel, cudaFuncAttributeMaxDynamicSharedMemorySize,
                         NS * DM * (int)sizeof(float));
    cudaFuncSetAttribute(gemm_scan_kernel, cudaFuncAttributeMaxDynamicSharedMemorySize,
                         GEMM_SMEM);

    bx_kernel<<<512, 256, NS * DM * sizeof(float)>>>(x, B_w, B_b);
    gemm_scan_kernel<<<SCAN_BLOCKS + GEMM_BLOCKS, 256, GEMM_SMEM>>>(x, A, gate_w, gate_b);
    combine_ln_kernel<<<T_TOK / 8, 256>>>(x, C_w, C_b, Dv, ln_g, ln_b, out);
}

// round 5
// speedup vs baseline: 1.2524x; 1.2524x over previous
#include <cuda_runtime.h>
#include <cuda_bf16.h>
#include <math.h>

// ---------------------------------------------------------------------------
// SimplifiedSSMLayer: B=8, S=4096, D_MODEL=1024, D_STATE=16
// Round 5: GEMM fragment loads via ldmatrix (6 LDSM vs 24 LDS per k-slice),
// BK=32 / 3-stage / single-sync pipeline; bx reverted to round-3 config.
// ---------------------------------------------------------------------------

#define BATCH   8
#define SEQ     4096
#define DM      1024
#define NS      16
#define T_TOK   (BATCH*SEQ)          // 32768

__device__ float g_Bx[T_TOK * NS];               // 2 MB
__device__ float g_states[T_TOK * NS];           // 2 MB
__device__ float g_gate[(size_t)T_TOK * DM];     // 128 MB

// ---------------------------------------------------------------------------
// K1: Bx = x @ B_w^T + B_b   (round-3 version: 256 blocks, 51us measured)
// ---------------------------------------------------------------------------
__global__ void __launch_bounds__(256) bx_kernel(const float* __restrict__ x,
                                                 const float* __restrict__ B_w,
                                                 const float* __restrict__ B_b)
{
    extern __shared__ float Bw_s[];  // [16][1024]
    const int tid = threadIdx.x;
    for (int i = tid; i < (NS * DM) / 4; i += 256)
        reinterpret_cast<float4*>(Bw_s)[i] = reinterpret_cast<const float4*>(B_w)[i];
    __syncthreads();

    const int w = tid >> 5, lane = tid & 31;
    const int tbase = blockIdx.x * 128 + w * 16;

    for (int g = 0; g < 4; ++g) {
        const int t0 = tbase + g * 4;
        float acc[4][NS];
#pragma unroll
        for (int tt = 0; tt < 4; ++tt)
#pragma unroll
            for (int n = 0; n < NS; ++n) acc[tt][n] = 0.f;

#pragma unroll 2
        for (int c = 0; c < 8; ++c) {
            const int k0 = c * 128 + lane * 4;
            float4 xv[4];
#pragma unroll
            for (int tt = 0; tt < 4; ++tt)
                xv[tt] = *reinterpret_cast<const float4*>(&x[(size_t)(t0 + tt) * DM + k0]);
#pragma unroll
            for (int n = 0; n < NS; ++n) {
                const float4 bw = *reinterpret_cast<const float4*>(&Bw_s[n * DM + k0]);
#pragma unroll
                for (int tt = 0; tt < 4; ++tt) {
                    acc[tt][n] = fmaf(xv[tt].x, bw.x, acc[tt][n]);
                    acc[tt][n] = fmaf(xv[tt].y, bw.y, acc[tt][n]);
                    acc[tt][n] = fmaf(xv[tt].z, bw.z, acc[tt][n]);
                    acc[tt][n] = fmaf(xv[tt].w, bw.w, acc[tt][n]);
                }
            }
        }
#pragma unroll
        for (int tt = 0; tt < 4; ++tt) {
            float outv = 0.f;
#pragma unroll
            for (int n = 0; n < NS; ++n) {
                float v = acc[tt][n];
                v += __shfl_xor_sync(0xffffffffu, v, 16);
                v += __shfl_xor_sync(0xffffffffu, v, 8);
                v += __shfl_xor_sync(0xffffffffu, v, 4);
                v += __shfl_xor_sync(0xffffffffu, v, 2);
                v += __shfl_xor_sync(0xffffffffu, v, 1);
                if (lane == n) outv = v;
            }
            if (lane < NS)
                g_Bx[(size_t)(t0 + tt) * NS + lane] = outv + B_b[lane];
        }
    }
}

// ---------------------------------------------------------------------------
// K2: scan (blocks 0..63) + tf32 mma.sync gate GEMM (blocks 64..2111)
// ---------------------------------------------------------------------------
#define GTM 128
#define GTN 128
#define GBK 32
#define GSTAGES (DM / GBK)                // 32
#define N_MTILES (T_TOK / GTM)            // 256
#define N_NTILES (DM / GTN)               // 8
#define GEMM_BLOCKS (N_MTILES * N_NTILES) // 2048
#define SCAN_BLOCKS 64

#define ROWSTRIDE 36                      // floats; 36 mod 32 = 4 -> ldsm conflict-free
#define A_FLOATS (GTM * ROWSTRIDE)        // 4608
#define STAGE_FLOATS (2 * A_FLOATS)       // 9216
#define STAGE_BYTES (STAGE_FLOATS * 4)    // 36864
#define NPIPE 3
#define GEMM_SMEM (NPIPE * STAGE_BYTES)   // 110592 -> 2 CTAs/SM

#define SCAN_CHUNK 64
#define SCAN_WARM  64

__device__ __forceinline__ unsigned smem_u32(const void* p) {
    unsigned a;
    asm("{ .reg .u64 t; cvta.to.shared.u64 t, %1; cvt.u32.u64 %0, t; }"
        : "=r"(a) : "l"(p));
    return a;
}
__device__ __forceinline__ void cp16(unsigned dst, const void* src) {
    asm volatile("cp.async.cg.shared.global [%0], [%1], 16;"
                 :: "r"(dst), "l"(src) : "memory");
}
__device__ __forceinline__ void ldsm4(unsigned& r0, unsigned& r1,
                                      unsigned& r2, unsigned& r3, unsigned a) {
    asm volatile("ldmatrix.sync.aligned.m8n8.x4.shared.b16 {%0,%1,%2,%3}, [%4];"
                 : "=r"(r0), "=r"(r1), "=r"(r2), "=r"(r3) : "r"(a));
}

__global__ void __launch_bounds__(256, 2) gemm_scan_kernel(
    const float* __restrict__ x, const float* __restrict__ A,
    const float* __restrict__ gate_w, const float* __restrict__ gate_b)
{
    extern __shared__ float smemf[];

    if (blockIdx.x < SCAN_BLOCKS) {
        // ------------------ parallel scan (contraction warm-up) ------------
        if (threadIdx.x >= 128) return;
        const int sb = blockIdx.x;
        const int warp = threadIdx.x >> 5, lane = threadIdx.x & 31;
        const int chunk = sb * 8 + warp * 2 + (lane >> 4); // 0..511
        const int i = lane & 15;
        const int batch = chunk >> 6;
        const int cib = chunk & 63;
        const int t0 = cib * SCAN_CHUNK;
        const int ts = (cib == 0) ? 0 : (t0 - SCAN_WARM);

        float a[NS];
#pragma unroll
        for (int j = 0; j < NS; ++j) a[j] = __ldg(&A[i * NS + j]);

        const float* bxp = g_Bx + (size_t)batch * SEQ * NS;
        float* stp = g_states + (size_t)batch * SEQ * NS;
        float s = 0.f;
        for (int t = ts; t < t0 + SCAN_CHUNK; ++t) {
            const float bx = bxp[t * NS + i];
            float sv[NS];
#pragma unroll
            for (int j = 0; j < NS; ++j) sv[j] = __shfl_sync(0xffffffffu, s, j, 16);
            float p0 = fmaf(a[0], sv[0], fmaf(a[1], sv[1], fmaf(a[2], sv[2], a[3] * sv[3])));
            float p1 = fmaf(a[4], sv[4], fmaf(a[5], sv[5], fmaf(a[6], sv[6], a[7] * sv[7])));
            float p2 = fmaf(a[8], sv[8], fmaf(a[9], sv[9], fmaf(a[10], sv[10], a[11] * sv[11])));
            float p3 = fmaf(a[12], sv[12], fmaf(a[13], sv[13], fmaf(a[14], sv[14], a[15] * sv[15])));
            s = tanhf(bx + ((p0 + p1) + (p2 + p3)));
            if (t >= t0) stp[t * NS + i] = s;
        }
        return;
    }

    // ------------------------- GEMM path --------------------------------
    const int tile = blockIdx.x - SCAN_BLOCKS;
    const int m0 = (tile >> 3) * GTM;
    const int n0 = (tile & 7) * GTN;

    const int tid = threadIdx.x;
    const int wid = tid >> 5;
    const int lane = tid & 31;
    const int wm = (wid & 3) * 32;      // warp M offset in tile
    const int wn = (wid >> 2) * 64;     // warp N offset in tile
    const int lq = lane >> 2;           // 0..7
    const int lr = lane & 3;            // 0..3

    const unsigned sbase = smem_u32(smemf);

    // ldmatrix per-thread row/col components (byte offsets within a stage)
    // A x4: mats {m0-7,k0-3},{m8-15,k0-3},{m0-7,k4-7},{m8-15,k4-7}
    const int a_row = wm + (lane & 7) + ((lane >> 3) & 1) * 8;   // + mi*16
    const int a_kx  = (lane >> 4) * 4;                           // + k0
    // B x4: mats {n0-7,k0-3},{n0-7,k4-7},{n8-15,k0-3},{n8-15,k4-7}
    const int b_row = wn + (lane & 7) + ((lane >> 4) & 1) * 8;   // + nip*16
    const int b_kx  = ((lane >> 3) & 1) * 4;                     // + k0

    // --- cp.async stage issue: 36KB per stage (A 18KB + B 18KB) ---
    auto cp_stage = [&](int s) {
        const int kc = s * GBK;
        const unsigned sA = sbase + (unsigned)(s % NPIPE) * STAGE_BYTES;
        const unsigned sB = sA + A_FLOATS * 4;
#pragma unroll
        for (int q = 0; q < 4; ++q) {
            const int j = tid + 256 * q;
            const int row = j >> 3;
            const int kg = j & 7;
            cp16(sA + row * (ROWSTRIDE * 4) + kg * 16,
                 &x[(size_t)(m0 + row) * DM + kc + kg * 4]);
            cp16(sB + row * (ROWSTRIDE * 4) + kg * 16,
                 &gate_w[(size_t)(n0 + row) * DM + kc + kg * 4]);
        }
        asm volatile("cp.async.commit_group;" ::: "memory");
    };

    float c[2][8][4];
#pragma unroll
    for (int mi = 0; mi < 2; ++mi)
#pragma unroll
        for (int ni = 0; ni < 8; ++ni)
#pragma unroll
            for (int r = 0; r < 4; ++r) c[mi][ni][r] = 0.f;

    cp_stage(0);
    cp_stage(1);

    for (int s = 0; s < GSTAGES; ++s) {
        asm volatile("cp.async.wait_group 1;" ::: "memory");
        __syncthreads();

        const unsigned stg = sbase + (unsigned)(s % NPIPE) * STAGE_BYTES;
        const unsigned aAddr0 = stg + (unsigned)((a_row)*ROWSTRIDE + a_kx) * 4u;
        const unsigned bAddr0 = stg + (unsigned)(A_FLOATS + (b_row)*ROWSTRIDE + b_kx) * 4u;

#pragma unroll
        for (int ks = 0; ks < 4; ++ks) {
            const int k0 = ks * 8;
            unsigned af[2][4];
#pragma unroll
            for (int mi = 0; mi < 2; ++mi)
                ldsm4(af[mi][0], af[mi][1], af[mi][2], af[mi][3],
                      aAddr0 + (unsigned)(mi * 16 * ROWSTRIDE + k0) * 4u);
            unsigned bf[8][2];
#pragma unroll
            for (int nip = 0; nip < 4; ++nip)
                ldsm4(bf[nip * 2][0], bf[nip * 2][1],
                      bf[nip * 2 + 1][0], bf[nip * 2 + 1][1],
                      bAddr0 + (unsigned)(nip * 16 * ROWSTRIDE + k0) * 4u);
#pragma unroll
            for (int mi = 0; mi < 2; ++mi)
#pragma unroll
                for (int ni = 0; ni < 8; ++ni) {
                    asm volatile(
                        "mma.sync.aligned.m16n8k8.row.col.f32.tf32.tf32.f32 "
                        "{%0,%1,%2,%3}, {%4,%5,%6,%7}, {%8,%9}, {%0,%1,%2,%3};"
                        : "+f"(c[mi][ni][0]), "+f"(c[mi][ni][1]),
                          "+f"(c[mi][ni][2]), "+f"(c[mi][ni][3])
                        : "r"(af[mi][0]), "r"(af[mi][1]),
                          "r"(af[mi][2]), "r"(af[mi][3]),
                          "r"(bf[ni][0]), "r"(bf[ni][1]));
                }
        }
        if (s + 2 < GSTAGES) cp_stage(s + 2);
    }

    // --- epilogue: silu(acc + gate_b) -> g_gate ---
#pragma unroll
    for (int ni = 0; ni < 8; ++ni) {
        const int col = n0 + wn + ni * 8 + lr * 2;
        const float2 gb = *reinterpret_cast<const float2*>(&gate_b[col]);
#pragma unroll
        for (int mi = 0; mi < 2; ++mi) {
            const int row0 = m0 + wm + mi * 16 + lq;
#pragma unroll
            for (int h = 0; h < 2; ++h) {
                const int row = row0 + h * 8;
                float z0 = c[mi][ni][h * 2 + 0] + gb.x;
                float z1 = c[mi][ni][h * 2 + 1] + gb.y;
                float2 o;
                o.x = z0 / (1.0f + __expf(-z0));
                o.y = z1 / (1.0f + __expf(-z1));
                *reinterpret_cast<float2*>(&g_gate[(size_t)row * DM + col]) = o;
            }
        }
    }
}

// ---------------------------------------------------------------------------
// K3: fused  so = states@C_w^T + C_b + D*x ; o = g*so+(1-g)*x ; r = o+x ; LN
// ---------------------------------------------------------------------------
__global__ void __launch_bounds__(256) combine_ln_kernel(
    const float* __restrict__ x, const float* __restrict__ C_w,
    const float* __restrict__ C_b, const float* __restrict__ Dv,
    const float* __restrict__ ln_g, const float* __restrict__ ln_b,
    float* __restrict__ out)
{
    __shared__ float st_s[8][NS];
    __shared__ float r_s[8][DM];
    __shared__ float wsum[8][8], wsq[8][8];
    __shared__ float mu_s[8], rs_s[8];

    const int tid = threadIdx.x;
    const int tok0 = blockIdx.x * 8;

    if (tid < 128)
        st_s[tid >> 4][tid & 15] =
            g_states[(size_t)(tok0 + (tid >> 4)) * NS + (tid & 15)];

    float cw[4][NS], cb[4], dv[4], lg[4], lb[4];
#pragma unroll
    for (int q = 0; q < 4; ++q) {
        const int e = tid + q * 256;
#pragma unroll
        for (int n4 = 0; n4 < 4; ++n4) {
            const float4 v = *reinterpret_cast<const float4*>(&C_w[e * NS + n4 * 4]);
            cw[q][n4 * 4 + 0] = v.x;
            cw[q][n4 * 4 + 1] = v.y;
            cw[q][n4 * 4 + 2] = v.z;
            cw[q][n4 * 4 + 3] = v.w;
        }
        cb[q] = C_b[e];
        dv[q] = Dv[e];
        lg[q] = ln_g[e];
        lb[q] = ln_b[e];
    }
    __syncthreads();

    const int warp = tid >> 5, lane = tid & 31;
    for (int r = 0; r < 8; ++r) {
        const size_t t = (size_t)(tok0 + r);
        float ps = 0.f, pq = 0.f;
#pragma unroll
        for (int q = 0; q < 4; ++q) {
            const int e = tid + q * 256;
            const float xv = x[t * DM + e];
            const float gv = g_gate[t * DM + e];
            float so = cb[q];
#pragma unroll
            for (int n = 0; n < NS; ++n) so = fmaf(st_s[r][n], cw[q][n], so);
            so = fmaf(dv[q], xv, so);
            const float o = fmaf(gv, so - xv, xv);
            const float rr = o + xv;
            r_s[r][e] = rr;
            ps += rr;
            pq += rr * rr;
        }
#pragma unroll
        for (int off = 16; off; off >>= 1) {
            ps += __shfl_xor_sync(0xffffffffu, ps, off);
            pq += __shfl_xor_sync(0xffffffffu, pq, off);
        }
        if (lane == 0) { wsum[r][warp] = ps; wsq[r][warp] = pq; }
    }
    __syncthreads();

    if (tid < 8) {
        float s = 0.f, s2 = 0.f;
#pragma unroll
        for (int w = 0; w < 8; ++w) { s += wsum[tid][w]; s2 += wsq[tid][w]; }
        const float mu = s * (1.0f / DM);
        float var = s2 * (1.0f / DM) - mu * mu;
        var = fmaxf(var, 0.f);
        mu_s[tid] = mu;
        rs_s[tid] = rsqrtf(var + 1e-5f);
    }
    __syncthreads();

    for (int r = 0; r < 8; ++r) {
        const size_t t = (size_t)(tok0 + r);
        const float mu = mu_s[r], rs = rs_s[r];
#pragma unroll
        for (int q = 0; q < 4; ++q) {
            const int e = tid + q * 256;
            out[t * DM + e] = (r_s[r][e] - mu) * rs * lg[q] + lb[q];
        }
    }
}

// ---------------------------------------------------------------------------
extern "C" void kernel_launch(void* const* d_in, const int* in_sizes, int n_in,
                              void* d_out, int out_size)
{
    const float* x      = (const float*)d_in[0];
    const float* A      = (const float*)d_in[1];
    const float* B_w    = (const float*)d_in[2];
    const float* B_b    = (const float*)d_in[3];
    const float* C_w    = (const float*)d_in[4];
    const float* C_b    = (const float*)d_in[5];
    const float* Dv     = (const float*)d_in[6];
    const float* gate_w = (const float*)d_in[7];
    const float* gate_b = (const float*)d_in[8];
    const float* ln_g   = (const float*)d_in[9];
    const float* ln_b   = (const float*)d_in[10];
    float* out = (float*)d_out;

    cudaFuncSetAttribute(bx_kernel, cudaFuncAttributeMaxDynamicSharedMemorySize,
                         NS * DM * (int)sizeof(float));
    cudaFuncSetAttribute(gemm_scan_kernel, cudaFuncAttributeMaxDynamicSharedMemorySize,
                         GEMM_SMEM);

    bx_kernel<<<256, 256, NS * DM * sizeof(float)>>>(x, B_w, B_b);
    gemm_scan_kernel<<<SCAN_BLOCKS + GEMM_BLOCKS, 256, GEMM_SMEM>>>(x, A, gate_w, gate_b);
    combine_ln_kernel<<<T_TOK / 8, 256>>>(x, C_w, C_b, Dv, ln_g, ln_b, out);
}